// round 4
// baseline (speedup 1.0000x reference)
#include <cuda_runtime.h>

#define T_DIM 200
#define B_DIM 64
#define E_DIM 64
#define NROWS (T_DIM * B_DIM)   // 12800
#define BH (B_DIM * E_DIM)      // 4096
#define LOG2E 1.4426950408889634f

// ---- scratch ----
__device__ float g_x1[NROWS * E_DIM];   // pre-scaled by 0.5
__device__ float g_y2[NROWS * E_DIM];
__device__ float g_y3[NROWS * E_DIM];
__device__ float g_q [NROWS * E_DIM];   // pre-scaled by 0.5
__device__ float g_ma[NROWS * E_DIM];
__device__ float g_t0[4 * NROWS * 64];  // 0=pc_a,1=pc_b,2=pv_a,3=pv_b
__device__ float g_part[8 * BH];

__device__ __forceinline__ float ex2f(float x) {
    float r; asm("ex2.approx.f32 %0, %1;" : "=f"(r) : "f"(x)); return r;
}
__device__ __forceinline__ float rcpf(float x) {
    float r; asm("rcp.approx.f32 %0, %1;" : "=f"(r) : "f"(x)); return r;
}
__device__ __forceinline__ float tanhf_a(float x) {
    float r; asm("tanh.approx.f32 %0, %1;" : "=f"(r) : "f"(x)); return r;
}
__device__ __forceinline__ float sigf(float v) {
    return rcpf(1.0f + ex2f(-v * LOG2E));
}
__device__ __forceinline__ float leakyf(float v) {
    return (v >= 0.0f) ? v : 0.3f * v;
}

// ============================================================================
// GEMM (HOUT=64), up to 5 towers per launch. act: 0=none, 1=leaky, 2=*0.5
// ============================================================================
struct GemmBatch {
    const float* X[5];
    const float* W[5];
    const float* B[5];
    float*       Y[5];
    int          act[5];
};

__global__ void __launch_bounds__(256) gemm64_k(GemmBatch gb)
{
    constexpr int ROWS = 128;
    __shared__ float Xt[64][ROWS + 4];
    __shared__ float Ws[64][64];
    __shared__ float Bs[64];

    const int tw = blockIdx.y;
    const float* __restrict__ X  = gb.X[tw];
    const float* __restrict__ W  = gb.W[tw];
    const float* __restrict__ Bp = gb.B[tw];
    float* __restrict__ Y        = gb.Y[tw];
    const int act = gb.act[tw];

    const int tid = threadIdx.x;
    const int r0  = blockIdx.x * ROWS;

    for (int idx = tid; idx < 64 * 64; idx += 256)
        Ws[idx >> 6][idx & 63] = W[idx];
    if (tid < 64) Bs[tid] = Bp ? Bp[tid] : 0.0f;
    // transpose load: consecutive lanes -> consecutive r => conflict-free STS
    for (int idx = tid; idx < ROWS * 16; idx += 256) {
        int r  = idx & 127;
        int k4 = (idx >> 7) << 2;
        float4 v = *(const float4*)&X[(size_t)(r0 + r) * 64 + k4];
        Xt[k4 + 0][r] = v.x; Xt[k4 + 1][r] = v.y;
        Xt[k4 + 2][r] = v.z; Xt[k4 + 3][r] = v.w;
    }
    __syncthreads();

    const int tc = tid & 15;
    const int tr = tid >> 4;
    float acc[8][4];
    #pragma unroll
    for (int a = 0; a < 8; a++)
        #pragma unroll
        for (int c = 0; c < 4; c++) acc[a][c] = 0.0f;

    #pragma unroll 8
    for (int k = 0; k < 64; k++) {
        float4 x0 = *(const float4*)&Xt[k][tr * 8];
        float4 x1 = *(const float4*)&Xt[k][tr * 8 + 4];
        float4 wv = *(const float4*)&Ws[k][tc * 4];
        float xr[8] = {x0.x, x0.y, x0.z, x0.w, x1.x, x1.y, x1.z, x1.w};
        float wr[4] = {wv.x, wv.y, wv.z, wv.w};
        #pragma unroll
        for (int a = 0; a < 8; a++)
            #pragma unroll
            for (int c = 0; c < 4; c++) acc[a][c] += xr[a] * wr[c];
    }

    #pragma unroll
    for (int a = 0; a < 8; a++) {
        float4 o; float* ov = (float*)&o;
        #pragma unroll
        for (int c = 0; c < 4; c++) {
            float v = acc[a][c] + Bs[tc * 4 + c];
            if (act == 1)      v = leakyf(v);
            else if (act == 2) v = v * 0.5f;
            ov[c] = v;
        }
        *(float4*)&Y[(size_t)(r0 + tr * 8 + a) * 64 + tc * 4] = o;
    }
}

// ============================================================================
// 2-phase cumsum: q = (y2 + cumsum(y3)/(t+1)) * 0.5
// ============================================================================
__global__ void __launch_bounds__(256) scan1_k()
{
    int id = blockIdx.x * 256 + threadIdx.x;
    int col = id & (BH - 1);
    int ch  = id >> 12;
    int t0 = ch * 25;
    float s = 0.0f;
    #pragma unroll
    for (int t = 0; t < 25; t++)
        s += g_y3[(size_t)(t0 + t) * BH + col];
    g_part[ch * BH + col] = s;
}

__global__ void __launch_bounds__(256) scan2_k()
{
    int id = blockIdx.x * 256 + threadIdx.x;
    int col = id & (BH - 1);
    int ch  = id >> 12;
    float acc = 0.0f;
    for (int c = 0; c < ch; c++) acc += g_part[c * BH + col];
    int t0 = ch * 25;
    #pragma unroll
    for (int t = 0; t < 25; t++) {
        size_t o = (size_t)(t0 + t) * BH + col;
        acc += g_y3[o];
        float invt = __fdividef(1.0f, (float)(t0 + t + 1));
        g_q[o] = (g_y2[o] + acc * invt) * 0.5f;
    }
}

// ============================================================================
// attention: 256 thr = 8 warps, 4 i's per warp, 32 i's per block, grid (7,64)
// s[i,j] = 0.5*sum_h w0[h]*tanh(x1s[j,h]+qs[i,h]) + 0.5*sum(w0)   (pre-scaled)
// m_a[i,:] += s * inputs[j,:]
// ============================================================================
__global__ void __launch_bounds__(256) attn_k(const float* __restrict__ inp,
                                              const float* __restrict__ w0)
{
    __shared__ __align__(16) float x1s[32][68];
    __shared__ __align__(16) float ins[32][68];
    __shared__ __align__(16) float qs[32][64];
    __shared__ __align__(16) float w0s[64];

    const int b    = blockIdx.y;
    const int bx   = blockIdx.x;                 // 0..6
    const int ibb  = (bx & 1) ? (6 - (bx >> 1)) : (bx >> 1);   // zigzag
    const int i0   = ibb * 32;
    const int tid  = threadIdx.x;
    const int wid  = tid >> 5;
    const int lane = tid & 31;
    const int iw   = wid << 2;                   // warp's first local i

    if (tid < 64) w0s[tid] = w0[tid];
    // qs: 32 rows x 64, float4 loads
    for (int idx = tid; idx < 32 * 16; idx += 256) {
        int r = idx >> 4, h4 = (idx & 15) << 2;
        int ii = i0 + r;
        float4 v = make_float4(0.f, 0.f, 0.f, 0.f);
        if (ii < T_DIM) v = *(const float4*)&g_q[(size_t)ii * BH + b * 64 + h4];
        *(float4*)&qs[r][h4] = v;
    }
    __syncthreads();

    float hw0 = 0.0f;
    #pragma unroll 16
    for (int h = 0; h < 64; h++) hw0 += w0s[h];
    hw0 *= 0.5f;

    float macc[4][2];
    #pragma unroll
    for (int k = 0; k < 4; k++) { macc[k][0] = 0.0f; macc[k][1] = 0.0f; }

    const int imax_blk = min(i0 + 31, T_DIM - 1);
    const int i_top    = min(i0 + iw + 3, T_DIM - 1);   // warp's largest valid i

    for (int j0 = 0; j0 <= imax_blk; j0 += 32) {
        __syncthreads();
        for (int idx = tid; idx < 32 * 16; idx += 256) {
            int jj = idx >> 4, h4 = (idx & 15) << 2;
            int j = j0 + jj;
            float4 vx = make_float4(0.f, 0.f, 0.f, 0.f);
            float4 vi = vx;
            if (j < T_DIM) {
                size_t o = (size_t)j * BH + b * 64 + h4;
                vx = *(const float4*)&g_x1[o];
                vi = *(const float4*)&inp[o];
            }
            *(float4*)&x1s[jj][h4] = vx;
            *(float4*)&ins[jj][h4] = vi;
        }
        __syncthreads();

        if (i_top >= j0) {       // warp-uniform
            const int j = j0 + lane;
            float d0 = 0.f, d1 = 0.f, d2 = 0.f, d3 = 0.f;
            #pragma unroll
            for (int h4 = 0; h4 < 64; h4 += 4) {
                float4 xv = *(const float4*)&x1s[lane][h4];
                float4 wv = *(const float4*)&w0s[h4];
                float4 q0 = *(const float4*)&qs[iw + 0][h4];
                float4 q1 = *(const float4*)&qs[iw + 1][h4];
                float4 q2 = *(const float4*)&qs[iw + 2][h4];
                float4 q3 = *(const float4*)&qs[iw + 3][h4];
                d0 += wv.x * tanhf_a(xv.x + q0.x); d1 += wv.x * tanhf_a(xv.x + q1.x);
                d2 += wv.x * tanhf_a(xv.x + q2.x); d3 += wv.x * tanhf_a(xv.x + q3.x);
                d0 += wv.y * tanhf_a(xv.y + q0.y); d1 += wv.y * tanhf_a(xv.y + q1.y);
                d2 += wv.y * tanhf_a(xv.y + q2.y); d3 += wv.y * tanhf_a(xv.y + q3.y);
                d0 += wv.z * tanhf_a(xv.z + q0.z); d1 += wv.z * tanhf_a(xv.z + q1.z);
                d2 += wv.z * tanhf_a(xv.z + q2.z); d3 += wv.z * tanhf_a(xv.z + q3.z);
                d0 += wv.w * tanhf_a(xv.w + q0.w); d1 += wv.w * tanhf_a(xv.w + q1.w);
                d2 += wv.w * tanhf_a(xv.w + q2.w); d3 += wv.w * tanhf_a(xv.w + q3.w);
            }
            const int ib = i0 + iw;
            float s0 = (j <= ib + 0 && j < T_DIM) ? fmaf(0.5f, d0, hw0) : 0.0f;
            float s1 = (j <= ib + 1 && j < T_DIM) ? fmaf(0.5f, d1, hw0) : 0.0f;
            float s2 = (j <= ib + 2 && j < T_DIM) ? fmaf(0.5f, d2, hw0) : 0.0f;
            float s3 = (j <= ib + 3 && j < T_DIM) ? fmaf(0.5f, d3, hw0) : 0.0f;

            #pragma unroll 8
            for (int jj = 0; jj < 32; jj++) {
                float v0 = ins[jj][lane];
                float v1 = ins[jj][lane + 32];
                float b0 = __shfl_sync(0xffffffffu, s0, jj);
                float b1 = __shfl_sync(0xffffffffu, s1, jj);
                float b2 = __shfl_sync(0xffffffffu, s2, jj);
                float b3 = __shfl_sync(0xffffffffu, s3, jj);
                macc[0][0] += b0 * v0; macc[0][1] += b0 * v1;
                macc[1][0] += b1 * v0; macc[1][1] += b1 * v1;
                macc[2][0] += b2 * v0; macc[2][1] += b2 * v1;
                macc[3][0] += b3 * v0; macc[3][1] += b3 * v1;
            }
        }
    }

    #pragma unroll
    for (int k = 0; k < 4; k++) {
        int i = i0 + iw + k;
        if (i < T_DIM) {
            size_t o = (size_t)i * BH + b * 64;
            g_ma[o + lane]      = macc[k][0];
            g_ma[o + lane + 32] = macc[k][1];
        }
    }
}

// ============================================================================
// fused L1 + final
// ============================================================================
struct L1FArgs {
    const float* W[4];
    const float* B[4];
};

__global__ void __launch_bounds__(256) l1f_k(L1FArgs la, float* __restrict__ out)
{
    constexpr int ROWS = 128;
    __shared__ float Xa[64][ROWS + 4];
    __shared__ float Xb[64][ROWS + 4];
    __shared__ float Wa[64][32];
    __shared__ float Wb[64][32];
    __shared__ float Ba[32], Bb[32];

    const int tid = threadIdx.x;
    const int r0  = blockIdx.x * ROWS;
    const int tc  = tid & 7;
    const int tr  = tid >> 3;

    float pcv[4];
    float res[2][4];

    #pragma unroll
    for (int p = 0; p < 2; p++) {
        const float* Ta = g_t0 + (size_t)(2 * p)     * NROWS * 64;
        const float* Tb = g_t0 + (size_t)(2 * p + 1) * NROWS * 64;

        __syncthreads();
        for (int idx = tid; idx < ROWS * 16; idx += 256) {
            int r  = idx & 127;
            int k4 = (idx >> 7) << 2;
            float4 va = *(const float4*)&Ta[(size_t)(r0 + r) * 64 + k4];
            float4 vb = *(const float4*)&Tb[(size_t)(r0 + r) * 64 + k4];
            Xa[k4 + 0][r] = va.x; Xa[k4 + 1][r] = va.y;
            Xa[k4 + 2][r] = va.z; Xa[k4 + 3][r] = va.w;
            Xb[k4 + 0][r] = vb.x; Xb[k4 + 1][r] = vb.y;
            Xb[k4 + 2][r] = vb.z; Xb[k4 + 3][r] = vb.w;
        }
        for (int idx = tid; idx < 64 * 32; idx += 256) {
            Wa[idx >> 5][idx & 31] = la.W[2 * p][idx];
            Wb[idx >> 5][idx & 31] = la.W[2 * p + 1][idx];
        }
        if (tid < 32) { Ba[tid] = la.B[2 * p][tid]; Bb[tid] = la.B[2 * p + 1][tid]; }
        __syncthreads();

        float aa[4][4], ab[4][4];
        #pragma unroll
        for (int a = 0; a < 4; a++)
            #pragma unroll
            for (int c = 0; c < 4; c++) { aa[a][c] = 0.0f; ab[a][c] = 0.0f; }

        #pragma unroll 8
        for (int k = 0; k < 64; k++) {
            float4 xa = *(const float4*)&Xa[k][tr * 4];
            float4 xb = *(const float4*)&Xb[k][tr * 4];
            float4 wa = *(const float4*)&Wa[k][tc * 4];
            float4 wb = *(const float4*)&Wb[k][tc * 4];
            float xar[4] = {xa.x, xa.y, xa.z, xa.w};
            float xbr[4] = {xb.x, xb.y, xb.z, xb.w};
            float war[4] = {wa.x, wa.y, wa.z, wa.w};
            float wbr[4] = {wb.x, wb.y, wb.z, wb.w};
            #pragma unroll
            for (int a = 0; a < 4; a++)
                #pragma unroll
                for (int c = 0; c < 4; c++) {
                    aa[a][c] += xar[a] * war[c];
                    ab[a][c] += xbr[a] * wbr[c];
                }
        }

        #pragma unroll
        for (int a = 0; a < 4; a++) {
            float z = 0.0f;
            #pragma unroll
            for (int c = 0; c < 4; c++) {
                float va = leakyf(aa[a][c] + Ba[tc * 4 + c]);
                float vb = leakyf(ab[a][c] + Bb[tc * 4 + c]);
                z += va * vb;
            }
            #pragma unroll
            for (int off = 1; off < 8; off <<= 1)
                z += __shfl_xor_sync(0xffffffffu, z, off);
            res[p][a] = z;
        }
        if (p == 0) {
            #pragma unroll
            for (int a = 0; a < 4; a++) pcv[a] = sigf(res[0][a]);
        }
    }

    if (tc == 0) {
        #pragma unroll
        for (int a = 0; a < 4; a++) {
            int row = r0 + tr * 4 + a;
            float pc = pcv[a];
            float pv = sigf(res[1][a]) * pc;
            out[row]         = pc;
            out[NROWS + row] = pv;
        }
    }
}

// ============================================================================
extern "C" void kernel_launch(void* const* d_in, const int* in_sizes, int n_in,
                              void* d_out, int out_size)
{
    (void)in_sizes; (void)n_in; (void)out_size;
    const float* inp     = (const float*)d_in[0];
    const float* w1k     = (const float*)d_in[1];
    const float* w1b     = (const float*)d_in[2];
    const float* w2k     = (const float*)d_in[3];
    const float* w3k     = (const float*)d_in[4];
    const float* w0k     = (const float*)d_in[5];
    const float* pc_a0_k = (const float*)d_in[6],  *pc_a0_b = (const float*)d_in[7];
    const float* pc_b0_k = (const float*)d_in[8],  *pc_b0_b = (const float*)d_in[9];
    const float* pc_a1_k = (const float*)d_in[10], *pc_a1_b = (const float*)d_in[11];
    const float* pc_b1_k = (const float*)d_in[12], *pc_b1_b = (const float*)d_in[13];
    const float* pv_a0_k = (const float*)d_in[14], *pv_a0_b = (const float*)d_in[15];
    const float* pv_b0_k = (const float*)d_in[16], *pv_b0_b = (const float*)d_in[17];
    const float* pv_a1_k = (const float*)d_in[18], *pv_a1_b = (const float*)d_in[19];
    const float* pv_b1_k = (const float*)d_in[20], *pv_b1_b = (const float*)d_in[21];

    float *x1, *y2, *y3, *ma, *t0;
    cudaGetSymbolAddress((void**)&x1, g_x1);
    cudaGetSymbolAddress((void**)&y2, g_y2);
    cudaGetSymbolAddress((void**)&y3, g_y3);
    cudaGetSymbolAddress((void**)&ma, g_ma);
    cudaGetSymbolAddress((void**)&t0, g_t0);

    // 1) x1 (scaled by 0.5), y2, y3, + inp-only L0 towers (pc_b0, pv_b0)
    GemmBatch A = {};
    A.X[0] = inp; A.W[0] = w1k;     A.B[0] = w1b;     A.Y[0] = x1;                           A.act[0] = 2;
    A.X[1] = inp; A.W[1] = w2k;     A.B[1] = nullptr; A.Y[1] = y2;                           A.act[1] = 0;
    A.X[2] = inp; A.W[2] = w3k;     A.B[2] = nullptr; A.Y[2] = y3;                           A.act[2] = 0;
    A.X[3] = inp; A.W[3] = pc_b0_k; A.B[3] = pc_b0_b; A.Y[3] = t0 + 1 * (size_t)NROWS * 64;  A.act[3] = 1;
    A.X[4] = inp; A.W[4] = pv_b0_k; A.B[4] = pv_b0_b; A.Y[4] = t0 + 3 * (size_t)NROWS * 64;  A.act[4] = 1;
    gemm64_k<<<dim3(NROWS / 128, 5), 256>>>(A);

    // 2) scan
    scan1_k<<<(8 * BH) / 256, 256>>>();
    scan2_k<<<(8 * BH) / 256, 256>>>();

    // 3) scores + m_a
    attn_k<<<dim3(7, B_DIM), 256>>>(inp, w0k);

    // 4) ma-based L0 towers
    GemmBatch L0 = {};
    L0.X[0] = ma; L0.W[0] = pc_a0_k; L0.B[0] = pc_a0_b; L0.Y[0] = t0 + 0 * (size_t)NROWS * 64; L0.act[0] = 1;
    L0.X[1] = ma; L0.W[1] = pv_a0_k; L0.B[1] = pv_a0_b; L0.Y[1] = t0 + 2 * (size_t)NROWS * 64; L0.act[1] = 1;
    gemm64_k<<<dim3(NROWS / 128, 2), 256>>>(L0);

    // 5) fused L1 + product-reduce + sigmoid
    L1FArgs la = {};
    la.W[0] = pc_a1_k; la.B[0] = pc_a1_b;
    la.W[1] = pc_b1_k; la.B[1] = pc_b1_b;
    la.W[2] = pv_a1_k; la.B[2] = pv_a1_b;
    la.W[3] = pv_b1_k; la.B[3] = pv_b1_b;
    l1f_k<<<NROWS / 128, 256>>>(la, (float*)d_out);
}

// round 5
// speedup vs baseline: 1.0756x; 1.0756x over previous
#include <cuda_runtime.h>

#define T_DIM 200
#define B_DIM 64
#define E_DIM 64
#define NROWS (T_DIM * B_DIM)   // 12800
#define BH (B_DIM * E_DIM)      // 4096
#define LOG2E 1.4426950408889634f

// ---- scratch ----
__device__ float g_x1[NROWS * E_DIM];   // pre-scaled by 0.5
__device__ float g_y2[NROWS * E_DIM];
__device__ float g_y3[NROWS * E_DIM];
__device__ float g_q [NROWS * E_DIM];   // pre-scaled by 0.5
__device__ float g_ma[NROWS * E_DIM];
__device__ float g_t0[4 * NROWS * 64];  // 0=pc_a,1=pc_b,2=pv_a,3=pv_b
__device__ float g_part[8 * BH];

// (i-block, j-chunk) tile list: 16 blocks per batch, balanced 1-2 tiles each
__constant__ int c_IBB[16] = {0,1,2,2,3,3,4,4,4,5,5,5,6,6,6,6};
__constant__ int c_JC [16] = {0,0,0,1,0,1,0,1,2,0,1,2,0,1,2,3};

__device__ __forceinline__ float ex2f(float x) {
    float r; asm("ex2.approx.f32 %0, %1;" : "=f"(r) : "f"(x)); return r;
}
__device__ __forceinline__ float rcpf(float x) {
    float r; asm("rcp.approx.f32 %0, %1;" : "=f"(r) : "f"(x)); return r;
}
__device__ __forceinline__ float tanhf_a(float x) {
    float r; asm("tanh.approx.f32 %0, %1;" : "=f"(r) : "f"(x)); return r;
}
__device__ __forceinline__ float sigf(float v) {
    return rcpf(1.0f + ex2f(-v * LOG2E));
}
__device__ __forceinline__ float leakyf(float v) {
    return (v >= 0.0f) ? v : 0.3f * v;
}

// ============================================================================
// GEMM (HOUT=64), up to 5 towers per launch. act: 0=none, 1=leaky, 2=*0.5
// ============================================================================
struct GemmBatch {
    const float* X[5];
    const float* W[5];
    const float* B[5];
    float*       Y[5];
    int          act[5];
};

__global__ void __launch_bounds__(256) gemm64_k(GemmBatch gb)
{
    constexpr int ROWS = 128;
    __shared__ float Xt[64][ROWS + 4];
    __shared__ float Ws[64][64];
    __shared__ float Bs[64];

    const int tw = blockIdx.y;
    const float* __restrict__ X  = gb.X[tw];
    const float* __restrict__ W  = gb.W[tw];
    const float* __restrict__ Bp = gb.B[tw];
    float* __restrict__ Y        = gb.Y[tw];
    const int act = gb.act[tw];

    const int tid = threadIdx.x;
    const int r0  = blockIdx.x * ROWS;

    for (int idx = tid; idx < 64 * 64; idx += 256)
        Ws[idx >> 6][idx & 63] = W[idx];
    if (tid < 64) Bs[tid] = Bp ? Bp[tid] : 0.0f;
    for (int idx = tid; idx < ROWS * 16; idx += 256) {
        int r  = idx & 127;
        int k4 = (idx >> 7) << 2;
        float4 v = *(const float4*)&X[(size_t)(r0 + r) * 64 + k4];
        Xt[k4 + 0][r] = v.x; Xt[k4 + 1][r] = v.y;
        Xt[k4 + 2][r] = v.z; Xt[k4 + 3][r] = v.w;
    }
    __syncthreads();

    const int tc = tid & 15;
    const int tr = tid >> 4;
    float acc[8][4];
    #pragma unroll
    for (int a = 0; a < 8; a++)
        #pragma unroll
        for (int c = 0; c < 4; c++) acc[a][c] = 0.0f;

    #pragma unroll 8
    for (int k = 0; k < 64; k++) {
        float4 x0 = *(const float4*)&Xt[k][tr * 8];
        float4 x1 = *(const float4*)&Xt[k][tr * 8 + 4];
        float4 wv = *(const float4*)&Ws[k][tc * 4];
        float xr[8] = {x0.x, x0.y, x0.z, x0.w, x1.x, x1.y, x1.z, x1.w};
        float wr[4] = {wv.x, wv.y, wv.z, wv.w};
        #pragma unroll
        for (int a = 0; a < 8; a++)
            #pragma unroll
            for (int c = 0; c < 4; c++) acc[a][c] += xr[a] * wr[c];
    }

    #pragma unroll
    for (int a = 0; a < 8; a++) {
        float4 o; float* ov = (float*)&o;
        #pragma unroll
        for (int c = 0; c < 4; c++) {
            float v = acc[a][c] + Bs[tc * 4 + c];
            if (act == 1)      v = leakyf(v);
            else if (act == 2) v = v * 0.5f;
            ov[c] = v;
        }
        *(float4*)&Y[(size_t)(r0 + tr * 8 + a) * 64 + tc * 4] = o;
    }
}

// ============================================================================
// scan phase 1 (+ zero g_ma)
// ============================================================================
__global__ void __launch_bounds__(256) scan1_k()
{
    int id = blockIdx.x * 256 + threadIdx.x;   // 32768 threads
    // zero m_a accumulator (float4)
    float4 z4 = make_float4(0.f, 0.f, 0.f, 0.f);
    float4* mz = (float4*)g_ma;
    for (int i = id; i < NROWS * 16; i += 32768) mz[i] = z4;

    int col = id & (BH - 1);
    int ch  = id >> 12;
    int t0 = ch * 25;
    float s = 0.0f;
    #pragma unroll
    for (int t = 0; t < 25; t++)
        s += g_y3[(size_t)(t0 + t) * BH + col];
    g_part[ch * BH + col] = s;
}

__global__ void __launch_bounds__(256) scan2_k()
{
    int id = blockIdx.x * 256 + threadIdx.x;
    int col = id & (BH - 1);
    int ch  = id >> 12;
    float acc = 0.0f;
    for (int c = 0; c < ch; c++) acc += g_part[c * BH + col];
    int t0 = ch * 25;
    #pragma unroll
    for (int t = 0; t < 25; t++) {
        size_t o = (size_t)(t0 + t) * BH + col;
        acc += g_y3[o];
        float invt = __fdividef(1.0f, (float)(t0 + t + 1));
        g_q[o] = (g_y2[o] + acc * invt) * 0.5f;
    }
}

// ============================================================================
// attention, tile-parallel: grid (16, 64). Block = 32 i x 64 j chunk
// (1-2 j-tiles of 32). 8 warps x 4 i. Partial m_a via atomicAdd (RED).
// ============================================================================
__global__ void __launch_bounds__(256, 4) attn_k(const float* __restrict__ inp,
                                                 const float* __restrict__ w0)
{
    __shared__ __align__(16) float x1s[32][68];
    __shared__ __align__(16) float ins[32][68];
    __shared__ __align__(16) float qs[32][64];
    __shared__ __align__(16) float w0s[64];

    const int b    = blockIdx.y;
    const int ibb  = c_IBB[blockIdx.x];
    const int jc   = c_JC[blockIdx.x];
    const int i0   = ibb * 32;
    const int tid  = threadIdx.x;
    const int wid  = tid >> 5;
    const int lane = tid & 31;
    const int iw   = wid << 2;

    if (tid < 64) w0s[tid] = w0[tid];
    for (int idx = tid; idx < 32 * 16; idx += 256) {
        int r = idx >> 4, h4 = (idx & 15) << 2;
        int ii = i0 + r;
        float4 v = make_float4(0.f, 0.f, 0.f, 0.f);
        if (ii < T_DIM) v = *(const float4*)&g_q[(size_t)ii * BH + b * 64 + h4];
        *(float4*)&qs[r][h4] = v;
    }
    __syncthreads();

    float hw0 = 0.0f;
    #pragma unroll 16
    for (int h = 0; h < 64; h++) hw0 += w0s[h];
    hw0 *= 0.5f;

    float macc[4][2];
    #pragma unroll
    for (int k = 0; k < 4; k++) { macc[k][0] = 0.0f; macc[k][1] = 0.0f; }

    const int ntiles = (2 * jc + 1 <= ibb) ? 2 : 1;

    for (int t = 0; t < ntiles; t++) {
        const int j0 = (2 * jc + t) * 32;
        if (t) __syncthreads();
        for (int idx = tid; idx < 32 * 16; idx += 256) {
            int jj = idx >> 4, h4 = (idx & 15) << 2;
            int j = j0 + jj;
            float4 vx = make_float4(0.f, 0.f, 0.f, 0.f);
            float4 vi = vx;
            if (j < T_DIM) {
                size_t o = (size_t)j * BH + b * 64 + h4;
                vx = *(const float4*)&g_x1[o];
                vi = *(const float4*)&inp[o];
            }
            *(float4*)&x1s[jj][h4] = vx;
            *(float4*)&ins[jj][h4] = vi;
        }
        __syncthreads();

        const int j = j0 + lane;
        float d0 = 0.f, d1 = 0.f, d2 = 0.f, d3 = 0.f;
        #pragma unroll
        for (int h4 = 0; h4 < 64; h4 += 4) {
            float4 xv = *(const float4*)&x1s[lane][h4];
            float4 wv = *(const float4*)&w0s[h4];
            float4 q0 = *(const float4*)&qs[iw + 0][h4];
            float4 q1 = *(const float4*)&qs[iw + 1][h4];
            float4 q2 = *(const float4*)&qs[iw + 2][h4];
            float4 q3 = *(const float4*)&qs[iw + 3][h4];
            d0 += wv.x * tanhf_a(xv.x + q0.x); d1 += wv.x * tanhf_a(xv.x + q1.x);
            d2 += wv.x * tanhf_a(xv.x + q2.x); d3 += wv.x * tanhf_a(xv.x + q3.x);
            d0 += wv.y * tanhf_a(xv.y + q0.y); d1 += wv.y * tanhf_a(xv.y + q1.y);
            d2 += wv.y * tanhf_a(xv.y + q2.y); d3 += wv.y * tanhf_a(xv.y + q3.y);
            d0 += wv.z * tanhf_a(xv.z + q0.z); d1 += wv.z * tanhf_a(xv.z + q1.z);
            d2 += wv.z * tanhf_a(xv.z + q2.z); d3 += wv.z * tanhf_a(xv.z + q3.z);
            d0 += wv.w * tanhf_a(xv.w + q0.w); d1 += wv.w * tanhf_a(xv.w + q1.w);
            d2 += wv.w * tanhf_a(xv.w + q2.w); d3 += wv.w * tanhf_a(xv.w + q3.w);
        }
        const int ib = i0 + iw;
        float s0 = (j <= ib + 0 && j < T_DIM) ? fmaf(0.5f, d0, hw0) : 0.0f;
        float s1 = (j <= ib + 1 && j < T_DIM) ? fmaf(0.5f, d1, hw0) : 0.0f;
        float s2 = (j <= ib + 2 && j < T_DIM) ? fmaf(0.5f, d2, hw0) : 0.0f;
        float s3 = (j <= ib + 3 && j < T_DIM) ? fmaf(0.5f, d3, hw0) : 0.0f;

        #pragma unroll 8
        for (int jj = 0; jj < 32; jj++) {
            float v0 = ins[jj][lane];
            float v1 = ins[jj][lane + 32];
            float b0 = __shfl_sync(0xffffffffu, s0, jj);
            float b1 = __shfl_sync(0xffffffffu, s1, jj);
            float b2 = __shfl_sync(0xffffffffu, s2, jj);
            float b3 = __shfl_sync(0xffffffffu, s3, jj);
            macc[0][0] += b0 * v0; macc[0][1] += b0 * v1;
            macc[1][0] += b1 * v0; macc[1][1] += b1 * v1;
            macc[2][0] += b2 * v0; macc[2][1] += b2 * v1;
            macc[3][0] += b3 * v0; macc[3][1] += b3 * v1;
        }
    }

    #pragma unroll
    for (int k = 0; k < 4; k++) {
        int i = i0 + iw + k;
        if (i < T_DIM) {
            size_t o = (size_t)i * BH + b * 64;
            atomicAdd(&g_ma[o + lane],      macc[k][0]);
            atomicAdd(&g_ma[o + lane + 32], macc[k][1]);
        }
    }
}

// ============================================================================
// fused L1 + final (64-row tiles -> 200 blocks)
// ============================================================================
struct L1FArgs {
    const float* W[4];
    const float* B[4];
};

__global__ void __launch_bounds__(256) l1f_k(L1FArgs la, float* __restrict__ out)
{
    constexpr int ROWS = 64;
    __shared__ float Xa[64][ROWS + 4];
    __shared__ float Xb[64][ROWS + 4];
    __shared__ float Wa[64][32];
    __shared__ float Wb[64][32];
    __shared__ float Ba[32], Bb[32];

    const int tid = threadIdx.x;
    const int r0  = blockIdx.x * ROWS;
    const int tc  = tid & 7;     // 8 col-groups * 4
    const int tr  = tid >> 3;    // 32 row-groups * 2

    float pcv[2];
    float res[2][2];

    #pragma unroll
    for (int p = 0; p < 2; p++) {
        const float* Ta = g_t0 + (size_t)(2 * p)     * NROWS * 64;
        const float* Tb = g_t0 + (size_t)(2 * p + 1) * NROWS * 64;

        __syncthreads();
        for (int idx = tid; idx < ROWS * 16; idx += 256) {
            int r  = idx & 63;
            int k4 = (idx >> 6) << 2;
            float4 va = *(const float4*)&Ta[(size_t)(r0 + r) * 64 + k4];
            float4 vb = *(const float4*)&Tb[(size_t)(r0 + r) * 64 + k4];
            Xa[k4 + 0][r] = va.x; Xa[k4 + 1][r] = va.y;
            Xa[k4 + 2][r] = va.z; Xa[k4 + 3][r] = va.w;
            Xb[k4 + 0][r] = vb.x; Xb[k4 + 1][r] = vb.y;
            Xb[k4 + 2][r] = vb.z; Xb[k4 + 3][r] = vb.w;
        }
        for (int idx = tid; idx < 64 * 32; idx += 256) {
            Wa[idx >> 5][idx & 31] = la.W[2 * p][idx];
            Wb[idx >> 5][idx & 31] = la.W[2 * p + 1][idx];
        }
        if (tid < 32) { Ba[tid] = la.B[2 * p][tid]; Bb[tid] = la.B[2 * p + 1][tid]; }
        __syncthreads();

        float aa[2][4], ab[2][4];
        #pragma unroll
        for (int a = 0; a < 2; a++)
            #pragma unroll
            for (int c = 0; c < 4; c++) { aa[a][c] = 0.0f; ab[a][c] = 0.0f; }

        #pragma unroll 8
        for (int k = 0; k < 64; k++) {
            float2 xa = *(const float2*)&Xa[k][tr * 2];
            float2 xb = *(const float2*)&Xb[k][tr * 2];
            float4 wa = *(const float4*)&Wa[k][tc * 4];
            float4 wb = *(const float4*)&Wb[k][tc * 4];
            float xar[2] = {xa.x, xa.y};
            float xbr[2] = {xb.x, xb.y};
            float war[4] = {wa.x, wa.y, wa.z, wa.w};
            float wbr[4] = {wb.x, wb.y, wb.z, wb.w};
            #pragma unroll
            for (int a = 0; a < 2; a++)
                #pragma unroll
                for (int c = 0; c < 4; c++) {
                    aa[a][c] += xar[a] * war[c];
                    ab[a][c] += xbr[a] * wbr[c];
                }
        }

        #pragma unroll
        for (int a = 0; a < 2; a++) {
            float z = 0.0f;
            #pragma unroll
            for (int c = 0; c < 4; c++) {
                float va = leakyf(aa[a][c] + Ba[tc * 4 + c]);
                float vb = leakyf(ab[a][c] + Bb[tc * 4 + c]);
                z += va * vb;
            }
            #pragma unroll
            for (int off = 1; off < 8; off <<= 1)
                z += __shfl_xor_sync(0xffffffffu, z, off);
            res[p][a] = z;
        }
        if (p == 0) {
            #pragma unroll
            for (int a = 0; a < 2; a++) pcv[a] = sigf(res[0][a]);
        }
    }

    if (tc == 0) {
        #pragma unroll
        for (int a = 0; a < 2; a++) {
            int row = r0 + tr * 2 + a;
            float pc = pcv[a];
            float pv = sigf(res[1][a]) * pc;
            out[row]         = pc;
            out[NROWS + row] = pv;
        }
    }
}

// ============================================================================
extern "C" void kernel_launch(void* const* d_in, const int* in_sizes, int n_in,
                              void* d_out, int out_size)
{
    (void)in_sizes; (void)n_in; (void)out_size;
    const float* inp     = (const float*)d_in[0];
    const float* w1k     = (const float*)d_in[1];
    const float* w1b     = (const float*)d_in[2];
    const float* w2k     = (const float*)d_in[3];
    const float* w3k     = (const float*)d_in[4];
    const float* w0k     = (const float*)d_in[5];
    const float* pc_a0_k = (const float*)d_in[6],  *pc_a0_b = (const float*)d_in[7];
    const float* pc_b0_k = (const float*)d_in[8],  *pc_b0_b = (const float*)d_in[9];
    const float* pc_a1_k = (const float*)d_in[10], *pc_a1_b = (const float*)d_in[11];
    const float* pc_b1_k = (const float*)d_in[12], *pc_b1_b = (const float*)d_in[13];
    const float* pv_a0_k = (const float*)d_in[14], *pv_a0_b = (const float*)d_in[15];
    const float* pv_b0_k = (const float*)d_in[16], *pv_b0_b = (const float*)d_in[17];
    const float* pv_a1_k = (const float*)d_in[18], *pv_a1_b = (const float*)d_in[19];
    const float* pv_b1_k = (const float*)d_in[20], *pv_b1_b = (const float*)d_in[21];

    float *x1, *y2, *y3, *ma, *t0;
    cudaGetSymbolAddress((void**)&x1, g_x1);
    cudaGetSymbolAddress((void**)&y2, g_y2);
    cudaGetSymbolAddress((void**)&y3, g_y3);
    cudaGetSymbolAddress((void**)&ma, g_ma);
    cudaGetSymbolAddress((void**)&t0, g_t0);

    // 1) x1 (scaled by 0.5), y2, y3, + inp-only L0 towers (pc_b0, pv_b0)
    GemmBatch A = {};
    A.X[0] = inp; A.W[0] = w1k;     A.B[0] = w1b;     A.Y[0] = x1;                           A.act[0] = 2;
    A.X[1] = inp; A.W[1] = w2k;     A.B[1] = nullptr; A.Y[1] = y2;                           A.act[1] = 0;
    A.X[2] = inp; A.W[2] = w3k;     A.B[2] = nullptr; A.Y[2] = y3;                           A.act[2] = 0;
    A.X[3] = inp; A.W[3] = pc_b0_k; A.B[3] = pc_b0_b; A.Y[3] = t0 + 1 * (size_t)NROWS * 64;  A.act[3] = 1;
    A.X[4] = inp; A.W[4] = pv_b0_k; A.B[4] = pv_b0_b; A.Y[4] = t0 + 3 * (size_t)NROWS * 64;  A.act[4] = 1;
    gemm64_k<<<dim3(NROWS / 128, 5), 256>>>(A);

    // 2) scan (scan1 also zeroes g_ma)
    scan1_k<<<(8 * BH) / 256, 256>>>();
    scan2_k<<<(8 * BH) / 256, 256>>>();

    // 3) scores + m_a (tile-parallel, atomic accumulate)
    attn_k<<<dim3(16, B_DIM), 256>>>(inp, w0k);

    // 4) ma-based L0 towers
    GemmBatch L0 = {};
    L0.X[0] = ma; L0.W[0] = pc_a0_k; L0.B[0] = pc_a0_b; L0.Y[0] = t0 + 0 * (size_t)NROWS * 64; L0.act[0] = 1;
    L0.X[1] = ma; L0.W[1] = pv_a0_k; L0.B[1] = pv_a0_b; L0.Y[1] = t0 + 2 * (size_t)NROWS * 64; L0.act[1] = 1;
    gemm64_k<<<dim3(NROWS / 128, 2), 256>>>(L0);

    // 5) fused L1 + product-reduce + sigmoid
    L1FArgs la = {};
    la.W[0] = pc_a1_k; la.B[0] = pc_a1_b;
    la.W[1] = pc_b1_k; la.B[1] = pc_b1_b;
    la.W[2] = pv_a1_k; la.B[2] = pv_a1_b;
    la.W[3] = pv_b1_k; la.B[3] = pv_b1_b;
    l1f_k<<<NROWS / 64, 256>>>(la, (float*)d_out);
}